// round 3
// baseline (speedup 1.0000x reference)
#include <cuda_runtime.h>
#include <cuda_bf16.h>

#define BINS        10
#define THREADS     256
#define CTAS_PER_SM 4
#define GRID        (148 * CTAS_PER_SM)   // 592: one wave at 4 CTAs/SM

// Global scratch (allocation-free). Invariant: zero at every kernel entry —
// zero-init at load, and the last CTA of each run resets after writing out.
__device__ float        g_binS[BINS];
__device__ float        g_binC[BINS];
__device__ unsigned int g_ticket;

// Register accumulation. Bin index matches reference bit-for-bit:
// g = |p-t| fp32, idx = trunc(g*10) clipped to 9.
// bce = -log(t ? p : 1-p) = -log(1 - g)  (t in {0,1}).
// acc[b] is packed f32x2 {S_b, C_b}; one predicated packed add per bin.
__device__ __forceinline__ void accum_elem(float p, float t,
                                           unsigned long long acc[BINS]) {
    float g   = fabsf(p - t);
    int   idx = min((int)(g * 10.0f), BINS - 1);
    float bce = -__logf(1.0f - g);
    unsigned long long v;
    asm("mov.b64 %0, {%1, %2};" : "=l"(v) : "f"(bce), "f"(1.0f));
    #pragma unroll
    for (int b = 0; b < BINS; b++) {
        asm volatile(
            "{\n\t"
            ".reg .pred p;\n\t"
            "setp.eq.s32 p, %1, %2;\n\t"
            "@p add.rn.f32x2 %0, %0, %3;\n\t"
            "}"
            : "+l"(acc[b]) : "r"(idx), "r"(b), "l"(v));
    }
}

__global__ void __launch_bounds__(THREADS, CTAS_PER_SM)
ghm_fused_kernel(const float* __restrict__ inp,
                 const float* __restrict__ tgt,
                 int n4, int n,
                 float* __restrict__ out) {
    __shared__ float2 hist[BINS * THREADS];   // 20 KB, used only for epilogue
    __shared__ bool   s_is_last;
    const int tid = threadIdx.x;

    unsigned long long acc[BINS];
    #pragma unroll
    for (int b = 0; b < BINS; b++) acc[b] = 0ull;

    const float4* __restrict__ P4 = (const float4*)inp;
    const float4* __restrict__ T4 = (const float4*)tgt;

    // Pure-register hot loop: no memory deps -> loads front-batch freely.
    #pragma unroll 2
    for (int i = blockIdx.x * THREADS + tid; i < n4; i += GRID * THREADS) {
        float4 p = __ldcs(&P4[i]);
        float4 t = __ldcs(&T4[i]);
        accum_elem(p.x, t.x, acc);
        accum_elem(p.y, t.y, acc);
        accum_elem(p.z, t.z, acc);
        accum_elem(p.w, t.w, acc);
    }
    // Scalar tail (n not divisible by 4).
    for (int i = n4 * 4 + blockIdx.x * THREADS + tid; i < n; i += GRID * THREADS)
        accum_elem(__ldcs(&inp[i]), __ldcs(&tgt[i]), acc);

    // Unpack accumulators into smem for the CTA reduction.
    #pragma unroll
    for (int b = 0; b < BINS; b++) {
        float s, c;
        asm("mov.b64 {%0, %1}, %2;" : "=f"(s), "=f"(c) : "l"(acc[b]));
        hist[b * THREADS + tid] = make_float2(s, c);
    }
    __syncthreads();

    // CTA tree reduction over the thread dimension, all bins per level.
    for (int s = THREADS / 2; s > 0; s >>= 1) {
        if (tid < s) {
            #pragma unroll
            for (int b = 0; b < BINS; b++) {
                float2 a = hist[b * THREADS + tid];
                float2 c = hist[b * THREADS + tid + s];
                hist[b * THREADS + tid] = make_float2(a.x + c.x, a.y + c.y);
            }
        }
        __syncthreads();
    }

    // Per-CTA partials into global bins.
    if (tid < BINS) {
        atomicAdd(&g_binS[tid], hist[tid * THREADS].x);
        atomicAdd(&g_binC[tid], hist[tid * THREADS].y);
    }
    __threadfence();
    __syncthreads();

    // Last CTA finalizes and resets state for the next graph replay.
    if (tid == 0)
        s_is_last = (atomicAdd(&g_ticket, 1u) == GRID - 1);
    __syncthreads();

    if (s_is_last && tid == 0) {
        __threadfence();
        float nb = 0.0f, accv = 0.0f;
        #pragma unroll
        for (int b = 0; b < BINS; b++) {
            float c = __ldcg(&g_binC[b]);
            float s = __ldcg(&g_binS[b]);
            if (c > 0.0f) {
                nb   += 1.0f;
                accv += s / c;
            }
        }
        out[0] = accv / fmaxf(nb, 1.0f);
        #pragma unroll
        for (int b = 0; b < BINS; b++) { g_binS[b] = 0.0f; g_binC[b] = 0.0f; }
        g_ticket = 0u;
    }
}

extern "C" void kernel_launch(void* const* d_in, const int* in_sizes, int n_in,
                              void* d_out, int out_size) {
    const float* inp = (const float*)d_in[0];
    const float* tgt = (const float*)d_in[1];
    float* out = (float*)d_out;
    int n  = in_sizes[0];
    int n4 = n >> 2;

    ghm_fused_kernel<<<GRID, THREADS>>>(inp, tgt, n4, n, out);
}

// round 4
// speedup vs baseline: 1.7346x; 1.7346x over previous
#include <cuda_runtime.h>
#include <cuda_bf16.h>

#define BINS     10
#define THREADS  256
#define GRID     1184   // 148 SMs * 8 CTAs

// Global scratch (allocation-free). Invariant: zero at every kernel entry —
// zero-initialized at load, last CTA of each run resets after writing out.
__device__ float        g_binS[BINS];
__device__ float        g_binC[BINS];
__device__ unsigned int g_ticket;

// Bin index matches reference bit-for-bit: g = |p-t| in fp32,
// idx = trunc(g*10) clipped to 9 (g >= 0 so trunc == floor).
// bce = -(t*log(p) + (1-t)*log(1-p)) = -log(1 - |p-t|) for t in {0,1}.
__device__ __forceinline__ void ghm_accum(float p, float t, float2* hist_tid) {
    float g   = fabsf(p - t);
    int   idx = min((int)(g * 10.0f), BINS - 1);
    float bce = -__logf(1.0f - g);
    // Per-thread-private slot hist[idx*THREADS + tid]: 32 lanes of a warp hit
    // 32 consecutive 8B slots -> conflict-free regardless of idx.
    float2* slot = hist_tid + idx * THREADS;
    float2  a = *slot;
    a.x += bce;
    a.y += 1.0f;
    *slot = a;
}

__global__ void __launch_bounds__(THREADS)
ghm_fused_kernel(const float* __restrict__ inp,
                 const float* __restrict__ tgt,
                 int n4, int n,
                 float* __restrict__ out) {
    __shared__ float2 hist[BINS * THREADS];   // 20 KB: [bin][tid]
    __shared__ bool   s_is_last;
    const int tid = threadIdx.x;

    #pragma unroll
    for (int b = 0; b < BINS; b++)
        hist[b * THREADS + tid] = make_float2(0.0f, 0.0f);
    __syncthreads();

    float2* hist_tid = &hist[tid];

    const float4* __restrict__ P4 = (const float4*)inp;
    const float4* __restrict__ T4 = (const float4*)tgt;

    // Grid-stride over float4 pairs. Unroll 4 -> up to 8 front-batched
    // LDG.128 per warp for deep MLP.
    #pragma unroll 4
    for (int i = blockIdx.x * THREADS + tid; i < n4; i += GRID * THREADS) {
        float4 p = P4[i];
        float4 t = T4[i];
        ghm_accum(p.x, t.x, hist_tid);
        ghm_accum(p.y, t.y, hist_tid);
        ghm_accum(p.z, t.z, hist_tid);
        ghm_accum(p.w, t.w, hist_tid);
    }
    // Scalar tail (n not divisible by 4).
    for (int i = n4 * 4 + blockIdx.x * THREADS + tid; i < n; i += GRID * THREADS)
        ghm_accum(inp[i], tgt[i], hist_tid);

    __syncthreads();

    // CTA tree reduction over the thread dimension, all bins per level.
    for (int s = THREADS / 2; s > 0; s >>= 1) {
        if (tid < s) {
            #pragma unroll
            for (int b = 0; b < BINS; b++) {
                float2 a = hist[b * THREADS + tid];
                float2 c = hist[b * THREADS + tid + s];
                hist[b * THREADS + tid] = make_float2(a.x + c.x, a.y + c.y);
            }
        }
        __syncthreads();
    }

    // Per-CTA partials into global bins.
    if (tid < BINS) {
        atomicAdd(&g_binS[tid], hist[tid * THREADS].x);
        atomicAdd(&g_binC[tid], hist[tid * THREADS].y);
    }
    __threadfence();
    __syncthreads();

    // Last CTA finalizes and resets state for the next graph replay.
    if (tid == 0)
        s_is_last = (atomicAdd(&g_ticket, 1u) == GRID - 1);
    __syncthreads();

    if (s_is_last && tid == 0) {
        __threadfence();
        float nb = 0.0f, accv = 0.0f;
        #pragma unroll
        for (int b = 0; b < BINS; b++) {
            float c = __ldcg(&g_binC[b]);
            float s = __ldcg(&g_binS[b]);
            if (c > 0.0f) {
                nb   += 1.0f;
                accv += s / c;
            }
        }
        out[0] = accv / fmaxf(nb, 1.0f);
        #pragma unroll
        for (int b = 0; b < BINS; b++) { g_binS[b] = 0.0f; g_binC[b] = 0.0f; }
        g_ticket = 0u;
    }
}

extern "C" void kernel_launch(void* const* d_in, const int* in_sizes, int n_in,
                              void* d_out, int out_size) {
    const float* inp = (const float*)d_in[0];
    const float* tgt = (const float*)d_in[1];
    float* out = (float*)d_out;
    int n  = in_sizes[0];
    int n4 = n >> 2;

    ghm_fused_kernel<<<GRID, THREADS>>>(inp, tgt, n4, n, out);
}